// round 11
// baseline (speedup 1.0000x reference)
#include <cuda_runtime.h>
#include <cstdint>

#define M_B 128
#define N_F 1024
#define K_F 1024
#define KSPLIT 8
#define NSLICE (KSPLIT * 2)        /* 16 partial slices (warp-level K-split) */
#define BN 64
#define KCHUNK (K_F / KSPLIT)      /* 128 */
#define GRID 128                   /* 16 nb-groups x 8 ks — single wave */
#define THREADS 512

#define SA_STRIDE 132              /* conflict-free frag loads */
#define SB_STRIDE 72               /* conflict-free frag loads */
#define SMEM_BYTES ((128 * SA_STRIDE + KCHUNK * SB_STRIDE) * 4)   /* 104448 */

// Scratch (device globals: no allocation allowed in kernel_launch)
__device__ float g_partial[NSLICE * M_B * N_F];   // 8 MB partial slices
__device__ unsigned int g_cnt8[8 * 32];            // 8 barrier counters, 128B apart

// ---------------------------------------------------------------------------
__device__ __forceinline__ void cp_async16(void* smem, const void* gmem) {
    uint32_t s = (uint32_t)__cvta_generic_to_shared(smem);
    asm volatile("cp.async.cg.shared.global [%0], [%1], 16;\n" :: "r"(s), "l"(gmem));
}
__device__ __forceinline__ void cp_commit() {
    asm volatile("cp.async.commit_group;\n");
}
template <int N>
__device__ __forceinline__ void cp_wait() {
    asm volatile("cp.async.wait_group %0;\n" :: "n"(N));
}
__device__ __forceinline__ uint32_t f2tf32(float x) {
    uint32_t r;
    asm("cvt.rna.tf32.f32 %0, %1;" : "=r"(r) : "f"(x));
    return r;
}

// ---------------------------------------------------------------------------
// Persistent kernel, 128 CTAs x 512 threads (single wave):
//   16 warps per CTA: warps [0,8) process K-half 0, warps [8,16) K-half 1 of
//   the 128-K chunk (warp-level split-K -> 4 warps/SMSP latency hiding, same
//   crossbar bytes). Monolithic fill (12 cp.async/thread), one wait+sync.
//   Each half writes its own partial slice (16 total). Spread-counter grid
//   barrier, then CTA b reduces 16 slices + bias + rank-2 epilogue for row b.
// ---------------------------------------------------------------------------
__global__ __launch_bounds__(THREADS, 1) void fused_kernel(
        const float* __restrict__ input,
        const float* __restrict__ codes,
        const float* __restrict__ weight,
        const float* __restrict__ A,
        const float* __restrict__ Bm,
        const float* __restrict__ bias,
        const float* __restrict__ bctx,
        float* __restrict__ out) {
    extern __shared__ float smem[];
    float (*sA)[SA_STRIDE] = reinterpret_cast<float(*)[SA_STRIDE]>(smem);
    float (*sB)[SB_STRIDE] = reinterpret_cast<float(*)[SB_STRIDE]>(smem + 128 * SA_STRIDE);
    __shared__ float s_red[16][2];
    __shared__ unsigned int s_target;

    int tid = threadIdx.x;
    int bid = blockIdx.x;

    int nb = (bid & 15) * BN;          // 16 nb-groups
    int ks = bid >> 4;                 // 8 ks
    int k_base = ks * KCHUNK;

    int wid = tid >> 5, lane = tid & 31;
    int kh = wid >> 3;                 // K-half within chunk
    int w8 = wid & 7;
    int wm = w8 & 3, wn = w8 >> 2;
    int m_base = wm * 32, n_base = wn * 32;
    int g = lane >> 2, q = lane & 3;
    int kk_base = kh * 64;

    // ---- issue ALL loads for the whole K-chunk (max MLP, 12/thread) ----
    {
        // sA: 128 rows x 32 float4/row = 4096; 8 per thread
        int a_row = tid >> 5, a_c4 = (tid & 31) * 4;
        #pragma unroll
        for (int t = 0; t < 8; t++) {
            int row = a_row + t * 16;
            cp_async16(&sA[row][a_c4], input + row * K_F + k_base + a_c4);
        }
        // sB: 128 rows x 16 float4/row = 2048; 4 per thread
        int b_row = tid >> 4, b_c4 = (tid & 15) * 4;
        #pragma unroll
        for (int t = 0; t < 4; t++) {
            int row = b_row + t * 32;
            cp_async16(&sB[row][b_c4], weight + (k_base + row) * N_F + nb + b_c4);
        }
        cp_commit();
    }

    // ---- prep (overlaps the cp.async fill): CTA b = bid ----
    float v0, v1, d0, d1;
    {
        int b = bid;
        float2 x = *reinterpret_cast<const float2*>(input + b * K_F + tid * 2);
        const float2* A2 = reinterpret_cast<const float2*>(A);
        float2 a0 = A2[tid * 2 + 0];
        float2 a1 = A2[tid * 2 + 1];
        float p0 = x.x * a0.x + x.y * a1.x;
        float p1 = x.x * a0.y + x.y * a1.y;
        #pragma unroll
        for (int off = 16; off > 0; off >>= 1) {
            p0 += __shfl_xor_sync(0xFFFFFFFFu, p0, off);
            p1 += __shfl_xor_sync(0xFFFFFFFFu, p1, off);
        }
        if (lane == 0) { s_red[wid][0] = p0; s_red[wid][1] = p1; }
        __syncthreads();
        float u0 = 0.f, u1 = 0.f;
        #pragma unroll
        for (int i = 0; i < 16; i++) { u0 += s_red[i][0]; u1 += s_red[i][1]; }
        float c00 = codes[b * 4 + 0], c01 = codes[b * 4 + 1];
        float c10 = codes[b * 4 + 2], c11 = codes[b * 4 + 3];
        v0 = u0 * c00 + u1 * c10;
        v1 = u0 * c01 + u1 * c11;
        d0 = c00;
        d1 = c11;
    }

    float acc[2][4][4];
    #pragma unroll
    for (int mi = 0; mi < 2; mi++)
        #pragma unroll
        for (int ni = 0; ni < 4; ni++)
            #pragma unroll
            for (int r = 0; r < 4; r++) acc[mi][ni][r] = 0.f;

    cp_wait<0>();
    __syncthreads();

    // ---- 8 kk steps per warp over this warp's K-half, no barriers ----
    #pragma unroll
    for (int i = 0; i < 8; i++) {
        int kk = kk_base + i * 8;
        uint32_t afr[2][4], bfr[4][2];
        #pragma unroll
        for (int mi = 0; mi < 2; mi++) {
            int r0 = m_base + mi * 16 + g;
            afr[mi][0] = f2tf32(sA[r0    ][kk + q    ]);
            afr[mi][1] = f2tf32(sA[r0 + 8][kk + q    ]);
            afr[mi][2] = f2tf32(sA[r0    ][kk + q + 4]);
            afr[mi][3] = f2tf32(sA[r0 + 8][kk + q + 4]);
        }
        #pragma unroll
        for (int ni = 0; ni < 4; ni++) {
            int c0 = n_base + ni * 8 + g;
            bfr[ni][0] = f2tf32(sB[kk + q    ][c0]);
            bfr[ni][1] = f2tf32(sB[kk + q + 4][c0]);
        }
        #pragma unroll
        for (int mi = 0; mi < 2; mi++)
            #pragma unroll
            for (int ni = 0; ni < 4; ni++) {
                asm volatile(
                    "mma.sync.aligned.m16n8k8.row.col.f32.tf32.tf32.f32 "
                    "{%0,%1,%2,%3}, {%4,%5,%6,%7}, {%8,%9}, {%0,%1,%2,%3};\n"
                    : "+f"(acc[mi][ni][0]), "+f"(acc[mi][ni][1]),
                      "+f"(acc[mi][ni][2]), "+f"(acc[mi][ni][3])
                    : "r"(afr[mi][0]), "r"(afr[mi][1]),
                      "r"(afr[mi][2]), "r"(afr[mi][3]),
                      "r"(bfr[ni][0]), "r"(bfr[ni][1]));
            }
    }

    // ---- write partial slice (ks*2 + kh) ----
    {
        float* part = g_partial + (ks * 2 + kh) * (M_B * N_F);
        #pragma unroll
        for (int mi = 0; mi < 2; mi++)
            #pragma unroll
            for (int ni = 0; ni < 4; ni++) {
                int row = m_base + mi * 16 + g;
                int col = nb + n_base + ni * 8 + q * 2;
                part[row * N_F + col]           = acc[mi][ni][0];
                part[row * N_F + col + 1]       = acc[mi][ni][1];
                part[(row + 8) * N_F + col]     = acc[mi][ni][2];
                part[(row + 8) * N_F + col + 1] = acc[mi][ni][3];
            }
    }

    // ========== grid barrier: 8 spread counters (16 arrivals each) ==========
    __threadfence();
    __syncthreads();
    if (tid == 0) {
        unsigned int ticket = atomicAdd(&g_cnt8[(bid & 7) * 32], 1u);
        s_target = (ticket / 16u + 1u) * 16u;
    }
    __syncthreads();
    if (tid < 8) {
        volatile unsigned int* c = &g_cnt8[tid * 32];
        unsigned int tgt = s_target;
        while (*c < tgt) { }
    }
    __syncthreads();
    __threadfence();

    // ============ Phase 2: reduce 16 slices + epilogue (CTA b = bid) =========
    {
        int b = bid;
        int j2 = tid * 2;
        float2 s = *reinterpret_cast<const float2*>(&g_partial[b * N_F + j2]);
        #pragma unroll
        for (int k = 1; k < NSLICE; k++) {
            float2 p = *reinterpret_cast<const float2*>(
                &g_partial[k * (M_B * N_F) + b * N_F + j2]);
            s.x += p.x; s.y += p.y;
        }
        float2 bi = *reinterpret_cast<const float2*>(bias + j2);
        float2 B0 = *reinterpret_cast<const float2*>(Bm + j2);
        float2 B1 = *reinterpret_cast<const float2*>(Bm + N_F + j2);
        float2 e0 = *reinterpret_cast<const float2*>(bctx + j2);
        float2 e1 = *reinterpret_cast<const float2*>(bctx + N_F + j2);

        float2 o;
        o.x = s.x + bi.x + v0 * B0.x + v1 * B1.x + d0 * e0.x + d1 * e1.x;
        o.y = s.y + bi.y + v0 * B0.y + v1 * B1.y + d0 * e0.y + d1 * e1.y;
        *reinterpret_cast<float2*>(out + b * N_F + j2) = o;
    }
}

extern "C" void kernel_launch(void* const* d_in, const int* in_sizes, int n_in,
                              void* d_out, int out_size) {
    const float* input  = (const float*)d_in[0];
    const float* codes  = (const float*)d_in[1];
    const float* weight = (const float*)d_in[2];
    const float* A      = (const float*)d_in[3];
    const float* Bm     = (const float*)d_in[4];
    const float* bias   = (const float*)d_in[5];
    const float* bctx   = (const float*)d_in[6];
    float* out = (float*)d_out;

    cudaFuncSetAttribute(fused_kernel,
                         cudaFuncAttributeMaxDynamicSharedMemorySize, SMEM_BYTES);

    fused_kernel<<<GRID, THREADS, SMEM_BYTES>>>(input, codes, weight, A, Bm,
                                                bias, bctx, out);
}

// round 12
// speedup vs baseline: 1.3509x; 1.3509x over previous
#include <cuda_runtime.h>
#include <cstdint>

#define M_B 128
#define N_F 1024
#define K_F 1024
#define KSPLIT 8
#define BN 64
#define KCHUNK (K_F / KSPLIT)      /* 128 */
#define GRID 128                   /* 16 nb-groups x 8 ks */

#define SA_STRIDE 132              /* conflict-free frag loads */
#define SB_STRIDE 72               /* conflict-free frag loads */
#define SMEM_BYTES ((128 * SA_STRIDE + KCHUNK * SB_STRIDE) * 4)   /* 104448 */

// Scratch (device globals: no allocation allowed in kernel_launch)
__device__ float g_partial[KSPLIT * M_B * N_F];   // 4 MB split-K partials

// ---------------------------------------------------------------------------
__device__ __forceinline__ void cp_async16(void* smem, const void* gmem) {
    uint32_t s = (uint32_t)__cvta_generic_to_shared(smem);
    asm volatile("cp.async.cg.shared.global [%0], [%1], 16;\n" :: "r"(s), "l"(gmem));
}
__device__ __forceinline__ void cp_commit() {
    asm volatile("cp.async.commit_group;\n");
}
template <int N>
__device__ __forceinline__ void cp_wait() {
    asm volatile("cp.async.wait_group %0;\n" :: "n"(N));
}
__device__ __forceinline__ uint32_t f2tf32(float x) {
    uint32_t r;
    asm("cvt.rna.tf32.f32 %0, %1;" : "=r"(r) : "f"(x));
    return r;
}

// ---------------------------------------------------------------------------
// Kernel 1: split-K tf32 GEMM, monolithic K-stage (R9 mainloop verbatim).
//   CTA (nb, ks): 128x64 tile of K-chunk ks -> partial slice ks. Nothing else.
// ---------------------------------------------------------------------------
__global__ __launch_bounds__(256, 1) void gemm_kernel(
        const float* __restrict__ input,
        const float* __restrict__ weight) {
    extern __shared__ float smem[];
    float (*sA)[SA_STRIDE] = reinterpret_cast<float(*)[SA_STRIDE]>(smem);
    float (*sB)[SB_STRIDE] = reinterpret_cast<float(*)[SB_STRIDE]>(smem + 128 * SA_STRIDE);

    int tid = threadIdx.x;
    int bid = blockIdx.x;

    int nb = (bid & 15) * BN;
    int ks = bid >> 4;
    int k_base = ks * KCHUNK;

    int wid = tid >> 5, lane = tid & 31;
    int wm = wid & 3, wn = wid >> 2;
    int m_base = wm * 32, n_base = wn * 32;
    int g = lane >> 2, q = lane & 3;

    // ---- issue ALL loads for the whole K-chunk (max MLP) ----
    {
        int a_row = tid >> 5, a_c4 = (tid & 31) * 4;
        #pragma unroll
        for (int t = 0; t < 16; t++) {
            int row = a_row + t * 8;
            cp_async16(&sA[row][a_c4], input + row * K_F + k_base + a_c4);
        }
        int b_row = tid >> 4, b_c4 = (tid & 15) * 4;
        #pragma unroll
        for (int t = 0; t < 8; t++) {
            int row = b_row + t * 16;
            cp_async16(&sB[row][b_c4], weight + (k_base + row) * N_F + nb + b_c4);
        }
        cp_commit();
    }

    float acc[2][4][4];
    #pragma unroll
    for (int mi = 0; mi < 2; mi++)
        #pragma unroll
        for (int ni = 0; ni < 4; ni++)
            #pragma unroll
            for (int r = 0; r < 4; r++) acc[mi][ni][r] = 0.f;

    cp_wait<0>();
    __syncthreads();

    // ---- 16 unrolled kk steps, no barriers ----
    #pragma unroll
    for (int kk = 0; kk < KCHUNK; kk += 8) {
        uint32_t afr[2][4], bfr[4][2];
        #pragma unroll
        for (int mi = 0; mi < 2; mi++) {
            int r0 = m_base + mi * 16 + g;
            afr[mi][0] = f2tf32(sA[r0    ][kk + q    ]);
            afr[mi][1] = f2tf32(sA[r0 + 8][kk + q    ]);
            afr[mi][2] = f2tf32(sA[r0    ][kk + q + 4]);
            afr[mi][3] = f2tf32(sA[r0 + 8][kk + q + 4]);
        }
        #pragma unroll
        for (int ni = 0; ni < 4; ni++) {
            int c0 = n_base + ni * 8 + g;
            bfr[ni][0] = f2tf32(sB[kk + q    ][c0]);
            bfr[ni][1] = f2tf32(sB[kk + q + 4][c0]);
        }
        #pragma unroll
        for (int mi = 0; mi < 2; mi++)
            #pragma unroll
            for (int ni = 0; ni < 4; ni++) {
                asm volatile(
                    "mma.sync.aligned.m16n8k8.row.col.f32.tf32.tf32.f32 "
                    "{%0,%1,%2,%3}, {%4,%5,%6,%7}, {%8,%9}, {%0,%1,%2,%3};\n"
                    : "+f"(acc[mi][ni][0]), "+f"(acc[mi][ni][1]),
                      "+f"(acc[mi][ni][2]), "+f"(acc[mi][ni][3])
                    : "r"(afr[mi][0]), "r"(afr[mi][1]),
                      "r"(afr[mi][2]), "r"(afr[mi][3]),
                      "r"(bfr[ni][0]), "r"(bfr[ni][1]));
            }
    }

    // ---- write split-K partials; kernel ends (no barrier, no phase 2) ----
    float* part = g_partial + ks * (M_B * N_F);
    #pragma unroll
    for (int mi = 0; mi < 2; mi++)
        #pragma unroll
        for (int ni = 0; ni < 4; ni++) {
            int row = m_base + mi * 16 + g;
            int col = nb + n_base + ni * 8 + q * 2;
            part[row * N_F + col]           = acc[mi][ni][0];
            part[row * N_F + col + 1]       = acc[mi][ni][1];
            part[(row + 8) * N_F + col]     = acc[mi][ni][2];
            part[(row + 8) * N_F + col + 1] = acc[mi][ni][3];
        }
}

// ---------------------------------------------------------------------------
// Kernel 2: CTA b -> prep (u = input_b . A -> v,d) fused with the 8-slice
// reduce + bias + rank-2 epilogue for row b. Prep's latency overlaps the
// partial-row loads (independent chains).
// ---------------------------------------------------------------------------
__global__ __launch_bounds__(256, 1) void finish_kernel(
        const float* __restrict__ input,
        const float* __restrict__ codes,
        const float* __restrict__ A,
        const float* __restrict__ Bm,
        const float* __restrict__ bias,
        const float* __restrict__ bctx,
        float* __restrict__ out) {
    __shared__ float s_red[8][2];
    int tid = threadIdx.x;
    int b = blockIdx.x;
    int lane = tid & 31, wid = tid >> 5;

    // kick off the partial-row loads first (8 independent float4 chains)
    int j4 = tid * 4;
    float4 p0v = *reinterpret_cast<const float4*>(&g_partial[b * N_F + j4]);
    float4 p1v = *reinterpret_cast<const float4*>(&g_partial[1 * M_B * N_F + b * N_F + j4]);
    float4 p2v = *reinterpret_cast<const float4*>(&g_partial[2 * M_B * N_F + b * N_F + j4]);
    float4 p3v = *reinterpret_cast<const float4*>(&g_partial[3 * M_B * N_F + b * N_F + j4]);
    float4 p4v = *reinterpret_cast<const float4*>(&g_partial[4 * M_B * N_F + b * N_F + j4]);
    float4 p5v = *reinterpret_cast<const float4*>(&g_partial[5 * M_B * N_F + b * N_F + j4]);
    float4 p6v = *reinterpret_cast<const float4*>(&g_partial[6 * M_B * N_F + b * N_F + j4]);
    float4 p7v = *reinterpret_cast<const float4*>(&g_partial[7 * M_B * N_F + b * N_F + j4]);

    // prep (independent of the loads above; overlaps their latency)
    float v0, v1, d0, d1;
    {
        float4 x = *reinterpret_cast<const float4*>(input + b * K_F + tid * 4);
        const float2* A2 = reinterpret_cast<const float2*>(A);
        float2 a0 = A2[tid * 4 + 0];
        float2 a1 = A2[tid * 4 + 1];
        float2 a2 = A2[tid * 4 + 2];
        float2 a3 = A2[tid * 4 + 3];
        float p0 = x.x * a0.x + x.y * a1.x + x.z * a2.x + x.w * a3.x;
        float p1 = x.x * a0.y + x.y * a1.y + x.z * a2.y + x.w * a3.y;
        #pragma unroll
        for (int off = 16; off > 0; off >>= 1) {
            p0 += __shfl_xor_sync(0xFFFFFFFFu, p0, off);
            p1 += __shfl_xor_sync(0xFFFFFFFFu, p1, off);
        }
        if (lane == 0) { s_red[wid][0] = p0; s_red[wid][1] = p1; }
        __syncthreads();
        float u0 = 0.f, u1 = 0.f;
        #pragma unroll
        for (int i = 0; i < 8; i++) { u0 += s_red[i][0]; u1 += s_red[i][1]; }
        float c00 = codes[b * 4 + 0], c01 = codes[b * 4 + 1];
        float c10 = codes[b * 4 + 2], c11 = codes[b * 4 + 3];
        v0 = u0 * c00 + u1 * c10;
        v1 = u0 * c01 + u1 * c11;
        d0 = c00;
        d1 = c11;
    }

    // reduce + epilogue
    float4 s;
    s.x = ((p0v.x + p1v.x) + (p2v.x + p3v.x)) + ((p4v.x + p5v.x) + (p6v.x + p7v.x));
    s.y = ((p0v.y + p1v.y) + (p2v.y + p3v.y)) + ((p4v.y + p5v.y) + (p6v.y + p7v.y));
    s.z = ((p0v.z + p1v.z) + (p2v.z + p3v.z)) + ((p4v.z + p5v.z) + (p6v.z + p7v.z));
    s.w = ((p0v.w + p1v.w) + (p2v.w + p3v.w)) + ((p4v.w + p5v.w) + (p6v.w + p7v.w));

    float4 bi = *reinterpret_cast<const float4*>(bias + j4);
    float4 B0 = *reinterpret_cast<const float4*>(Bm + j4);
    float4 B1 = *reinterpret_cast<const float4*>(Bm + N_F + j4);
    float4 e0 = *reinterpret_cast<const float4*>(bctx + j4);
    float4 e1 = *reinterpret_cast<const float4*>(bctx + N_F + j4);

    float4 o;
    o.x = s.x + bi.x + v0 * B0.x + v1 * B1.x + d0 * e0.x + d1 * e1.x;
    o.y = s.y + bi.y + v0 * B0.y + v1 * B1.y + d0 * e0.y + d1 * e1.y;
    o.z = s.z + bi.z + v0 * B0.z + v1 * B1.z + d0 * e0.z + d1 * e1.z;
    o.w = s.w + bi.w + v0 * B0.w + v1 * B1.w + d0 * e0.w + d1 * e1.w;
    *reinterpret_cast<float4*>(out + b * N_F + j4) = o;
}

extern "C" void kernel_launch(void* const* d_in, const int* in_sizes, int n_in,
                              void* d_out, int out_size) {
    const float* input  = (const float*)d_in[0];
    const float* codes  = (const float*)d_in[1];
    const float* weight = (const float*)d_in[2];
    const float* A      = (const float*)d_in[3];
    const float* Bm     = (const float*)d_in[4];
    const float* bias   = (const float*)d_in[5];
    const float* bctx   = (const float*)d_in[6];
    float* out = (float*)d_out;

    cudaFuncSetAttribute(gemm_kernel,
                         cudaFuncAttributeMaxDynamicSharedMemorySize, SMEM_BYTES);

    gemm_kernel<<<GRID, 256, SMEM_BYTES>>>(input, weight);
    finish_kernel<<<M_B, 256>>>(input, codes, A, Bm, bias, bctx, out);
}

// round 13
// speedup vs baseline: 1.3832x; 1.0240x over previous
#include <cuda_runtime.h>
#include <cstdint>

#define M_B 128
#define N_F 1024
#define K_F 1024
#define KSPLIT 8
#define BN 64
#define KCHUNK (K_F / KSPLIT)      /* 128 */
#define GRID 128                   /* 16 nb-groups x 8 ks */

#define SA_STRIDE 132              /* conflict-free frag loads */
#define SB_STRIDE 72               /* conflict-free frag loads */
#define SMEM_BYTES ((128 * SA_STRIDE + KCHUNK * SB_STRIDE) * 4)   /* 104448 */

// Scratch (device globals: no allocation allowed in kernel_launch)
__device__ float g_partial[KSPLIT * M_B * N_F];   // 4 MB split-K partials

// ---------------------------------------------------------------------------
__device__ __forceinline__ void cp_async16(void* smem, const void* gmem) {
    uint32_t s = (uint32_t)__cvta_generic_to_shared(smem);
    asm volatile("cp.async.cg.shared.global [%0], [%1], 16;\n" :: "r"(s), "l"(gmem));
}
__device__ __forceinline__ void cp_commit() {
    asm volatile("cp.async.commit_group;\n");
}
template <int N>
__device__ __forceinline__ void cp_wait() {
    asm volatile("cp.async.wait_group %0;\n" :: "n"(N));
}
__device__ __forceinline__ uint32_t f2tf32(float x) {
    uint32_t r;
    asm("cvt.rna.tf32.f32 %0, %1;" : "=r"(r) : "f"(x));
    return r;
}

// ---------------------------------------------------------------------------
// Kernel 1: split-K tf32 GEMM, monolithic K-stage (proven R12 mainloop).
//   CTA (nb, ks): 128x64 tile of K-chunk ks -> partial slice ks.
//   Signals dependent launch right after its partial stores.
// ---------------------------------------------------------------------------
__global__ __launch_bounds__(256, 1) void gemm_kernel(
        const float* __restrict__ input,
        const float* __restrict__ weight) {
    extern __shared__ float smem[];
    float (*sA)[SA_STRIDE] = reinterpret_cast<float(*)[SA_STRIDE]>(smem);
    float (*sB)[SB_STRIDE] = reinterpret_cast<float(*)[SB_STRIDE]>(smem + 128 * SA_STRIDE);

    int tid = threadIdx.x;
    int bid = blockIdx.x;

    int nb = (bid & 15) * BN;
    int ks = bid >> 4;
    int k_base = ks * KCHUNK;

    int wid = tid >> 5, lane = tid & 31;
    int wm = wid & 3, wn = wid >> 2;
    int m_base = wm * 32, n_base = wn * 32;
    int g = lane >> 2, q = lane & 3;

    // ---- issue ALL loads for the whole K-chunk (max MLP) ----
    {
        int a_row = tid >> 5, a_c4 = (tid & 31) * 4;
        #pragma unroll
        for (int t = 0; t < 16; t++) {
            int row = a_row + t * 8;
            cp_async16(&sA[row][a_c4], input + row * K_F + k_base + a_c4);
        }
        int b_row = tid >> 4, b_c4 = (tid & 15) * 4;
        #pragma unroll
        for (int t = 0; t < 8; t++) {
            int row = b_row + t * 16;
            cp_async16(&sB[row][b_c4], weight + (k_base + row) * N_F + nb + b_c4);
        }
        cp_commit();
    }

    float acc[2][4][4];
    #pragma unroll
    for (int mi = 0; mi < 2; mi++)
        #pragma unroll
        for (int ni = 0; ni < 4; ni++)
            #pragma unroll
            for (int r = 0; r < 4; r++) acc[mi][ni][r] = 0.f;

    cp_wait<0>();
    __syncthreads();

    // ---- 16 unrolled kk steps, no barriers ----
    #pragma unroll
    for (int kk = 0; kk < KCHUNK; kk += 8) {
        uint32_t afr[2][4], bfr[4][2];
        #pragma unroll
        for (int mi = 0; mi < 2; mi++) {
            int r0 = m_base + mi * 16 + g;
            afr[mi][0] = f2tf32(sA[r0    ][kk + q    ]);
            afr[mi][1] = f2tf32(sA[r0 + 8][kk + q    ]);
            afr[mi][2] = f2tf32(sA[r0    ][kk + q + 4]);
            afr[mi][3] = f2tf32(sA[r0 + 8][kk + q + 4]);
        }
        #pragma unroll
        for (int ni = 0; ni < 4; ni++) {
            int c0 = n_base + ni * 8 + g;
            bfr[ni][0] = f2tf32(sB[kk + q    ][c0]);
            bfr[ni][1] = f2tf32(sB[kk + q + 4][c0]);
        }
        #pragma unroll
        for (int mi = 0; mi < 2; mi++)
            #pragma unroll
            for (int ni = 0; ni < 4; ni++) {
                asm volatile(
                    "mma.sync.aligned.m16n8k8.row.col.f32.tf32.tf32.f32 "
                    "{%0,%1,%2,%3}, {%4,%5,%6,%7}, {%8,%9}, {%0,%1,%2,%3};\n"
                    : "+f"(acc[mi][ni][0]), "+f"(acc[mi][ni][1]),
                      "+f"(acc[mi][ni][2]), "+f"(acc[mi][ni][3])
                    : "r"(afr[mi][0]), "r"(afr[mi][1]),
                      "r"(afr[mi][2]), "r"(afr[mi][3]),
                      "r"(bfr[ni][0]), "r"(bfr[ni][1]));
            }
    }

    // ---- write split-K partials ----
    float* part = g_partial + ks * (M_B * N_F);
    #pragma unroll
    for (int mi = 0; mi < 2; mi++)
        #pragma unroll
        for (int ni = 0; ni < 4; ni++) {
            int row = m_base + mi * 16 + g;
            int col = nb + n_base + ni * 8 + q * 2;
            part[row * N_F + col]           = acc[mi][ni][0];
            part[row * N_F + col + 1]       = acc[mi][ni][1];
            part[(row + 8) * N_F + col]     = acc[mi][ni][2];
            part[(row + 8) * N_F + col + 1] = acc[mi][ni][3];
        }

    // allow the dependent grid to start its preamble
    asm volatile("griddepcontrol.launch_dependents;");
}

// ---------------------------------------------------------------------------
// Kernel 2 (PDL): preamble = prep + epilogue-vector loads (none produced by
// kernel 1), then griddepcontrol.wait, then partial loads + sum + store.
// ---------------------------------------------------------------------------
__global__ __launch_bounds__(256, 1) void finish_kernel(
        const float* __restrict__ input,
        const float* __restrict__ codes,
        const float* __restrict__ A,
        const float* __restrict__ Bm,
        const float* __restrict__ bias,
        const float* __restrict__ bctx,
        float* __restrict__ out) {
    __shared__ float s_red[8][2];
    int tid = threadIdx.x;
    int b = blockIdx.x;
    int lane = tid & 31, wid = tid >> 5;
    int j4 = tid * 4;

    // ---------- preamble (independent of kernel 1's writes) ----------
    float4 bi = *reinterpret_cast<const float4*>(bias + j4);
    float4 B0 = *reinterpret_cast<const float4*>(Bm + j4);
    float4 B1 = *reinterpret_cast<const float4*>(Bm + N_F + j4);
    float4 e0 = *reinterpret_cast<const float4*>(bctx + j4);
    float4 e1 = *reinterpret_cast<const float4*>(bctx + N_F + j4);

    float v0, v1, d0, d1;
    {
        float4 x = *reinterpret_cast<const float4*>(input + b * K_F + tid * 4);
        const float2* A2 = reinterpret_cast<const float2*>(A);
        float2 a0 = A2[tid * 4 + 0];
        float2 a1 = A2[tid * 4 + 1];
        float2 a2 = A2[tid * 4 + 2];
        float2 a3 = A2[tid * 4 + 3];
        float p0 = x.x * a0.x + x.y * a1.x + x.z * a2.x + x.w * a3.x;
        float p1 = x.x * a0.y + x.y * a1.y + x.z * a2.y + x.w * a3.y;
        #pragma unroll
        for (int off = 16; off > 0; off >>= 1) {
            p0 += __shfl_xor_sync(0xFFFFFFFFu, p0, off);
            p1 += __shfl_xor_sync(0xFFFFFFFFu, p1, off);
        }
        if (lane == 0) { s_red[wid][0] = p0; s_red[wid][1] = p1; }
        __syncthreads();
        float u0 = 0.f, u1 = 0.f;
        #pragma unroll
        for (int i = 0; i < 8; i++) { u0 += s_red[i][0]; u1 += s_red[i][1]; }
        float c00 = codes[b * 4 + 0], c01 = codes[b * 4 + 1];
        float c10 = codes[b * 4 + 2], c11 = codes[b * 4 + 3];
        v0 = u0 * c00 + u1 * c10;
        v1 = u0 * c01 + u1 * c11;
        d0 = c00;
        d1 = c11;
    }

    // ---------- wait for upstream grid's stores to be visible ----------
    asm volatile("griddepcontrol.wait;" ::: "memory");

    // ---------- partial loads (8 independent float4 chains) + sum ----------
    float4 p0v = *reinterpret_cast<const float4*>(&g_partial[b * N_F + j4]);
    float4 p1v = *reinterpret_cast<const float4*>(&g_partial[1 * M_B * N_F + b * N_F + j4]);
    float4 p2v = *reinterpret_cast<const float4*>(&g_partial[2 * M_B * N_F + b * N_F + j4]);
    float4 p3v = *reinterpret_cast<const float4*>(&g_partial[3 * M_B * N_F + b * N_F + j4]);
    float4 p4v = *reinterpret_cast<const float4*>(&g_partial[4 * M_B * N_F + b * N_F + j4]);
    float4 p5v = *reinterpret_cast<const float4*>(&g_partial[5 * M_B * N_F + b * N_F + j4]);
    float4 p6v = *reinterpret_cast<const float4*>(&g_partial[6 * M_B * N_F + b * N_F + j4]);
    float4 p7v = *reinterpret_cast<const float4*>(&g_partial[7 * M_B * N_F + b * N_F + j4]);

    float4 s;
    s.x = ((p0v.x + p1v.x) + (p2v.x + p3v.x)) + ((p4v.x + p5v.x) + (p6v.x + p7v.x));
    s.y = ((p0v.y + p1v.y) + (p2v.y + p3v.y)) + ((p4v.y + p5v.y) + (p6v.y + p7v.y));
    s.z = ((p0v.z + p1v.z) + (p2v.z + p3v.z)) + ((p4v.z + p5v.z) + (p6v.z + p7v.z));
    s.w = ((p0v.w + p1v.w) + (p2v.w + p3v.w)) + ((p4v.w + p5v.w) + (p6v.w + p7v.w));

    float4 o;
    o.x = s.x + bi.x + v0 * B0.x + v1 * B1.x + d0 * e0.x + d1 * e1.x;
    o.y = s.y + bi.y + v0 * B0.y + v1 * B1.y + d0 * e0.y + d1 * e1.y;
    o.z = s.z + bi.z + v0 * B0.z + v1 * B1.z + d0 * e0.z + d1 * e1.z;
    o.w = s.w + bi.w + v0 * B0.w + v1 * B1.w + d0 * e0.w + d1 * e1.w;
    *reinterpret_cast<float4*>(out + b * N_F + j4) = o;
}

extern "C" void kernel_launch(void* const* d_in, const int* in_sizes, int n_in,
                              void* d_out, int out_size) {
    const float* input  = (const float*)d_in[0];
    const float* codes  = (const float*)d_in[1];
    const float* weight = (const float*)d_in[2];
    const float* A      = (const float*)d_in[3];
    const float* Bm     = (const float*)d_in[4];
    const float* bias   = (const float*)d_in[5];
    const float* bctx   = (const float*)d_in[6];
    float* out = (float*)d_out;

    cudaFuncSetAttribute(gemm_kernel,
                         cudaFuncAttributeMaxDynamicSharedMemorySize, SMEM_BYTES);

    gemm_kernel<<<GRID, 256, SMEM_BYTES>>>(input, weight);

    // finish_kernel with programmatic dependent launch (overlaps gemm tail)
    cudaLaunchConfig_t cfg = {};
    cfg.gridDim = dim3(M_B);
    cfg.blockDim = dim3(256);
    cfg.dynamicSmemBytes = 0;
    cfg.stream = 0;
    cudaLaunchAttribute at[1];
    at[0].id = cudaLaunchAttributeProgrammaticStreamSerialization;
    at[0].val.programmaticStreamSerializationAllowed = 1;
    cfg.attrs = at;
    cfg.numAttrs = 1;
    cudaLaunchKernelEx(&cfg, finish_kernel, input, codes, A, Bm, bias, bctx, out);
}